// round 5
// baseline (speedup 1.0000x reference)
#include <cuda_runtime.h>
#include <math.h>

// ---------------------------------------------------------------------------
// PhysicalLayer forward, sm_103a.
//   FO = M f M^T, M = F*T (F = 500-pt DFT, T Toeplitz from separable Q1).
//   M built in O(N^2) by sliding-window recurrence; 2 apply GEMMs with
//   pack-free f32x2 inner loop; warp-per-emitter Parseval intensities;
//   scatter + noise model. All setup fused into one prep kernel.
// ---------------------------------------------------------------------------

#define GN  500
#define TK  64
#define TR  32
#define KK  50
#define MTS 512
#define SEG 63

typedef unsigned long long u64;

__device__ float2 g_field[GN * GN];
__device__ float2 g_A[GN * GN];
__device__ float2 g_B[GN * GN];
__device__ float2 g_MT[GN * MTS];   // MT[m*512 + k] = M[k,m] (cols 500.. stay 0)
__device__ float  g_tg[GN * GN];
__device__ float2 g_p[1024];
__device__ float2 g_W500f[GN];
__device__ float2 g_W500i[GN];
__device__ float  g_intens[128];
__device__ float  g_canvas[2 * 200 * 200];

// ---------------- f32x2 packed helpers -------------------------------------
__device__ __forceinline__ u64 ffma2(u64 a, u64 b, u64 c) {
    u64 d;
    asm("fma.rn.f32x2 %0, %1, %2, %3;" : "=l"(d) : "l"(a), "l"(b), "l"(c));
    return d;
}
__device__ __forceinline__ float2 unpk(u64 v) {
    float lo, hi;
    asm("mov.b64 {%0, %1}, %2;" : "=f"(lo), "=f"(hi) : "l"(v));
    return make_float2(lo, hi);
}

// ---------------- fused prep: tables + zero + field + tg -------------------
__global__ void k_prep(const float* __restrict__ mp,
                       const float* __restrict__ mr,
                       const float2* __restrict__ B1,
                       const float* __restrict__ gam, float sK) {
    int i = blockIdx.x * blockDim.x + threadIdx.x;
    const double PI = 3.14159265358979323846;
    if (i < 1024) {
        float2 v = make_float2(0.f, 0.f);
        if (i < 1000) {
            double alpha = PI * 1.33 / (5.61e-7 * 0.006);
            double x = (double)(i - 499) * 1e-6;
            double th = alpha * x * x;
            double s, c;
            sincos(th, &s, &c);
            v = make_float2((float)c, (float)s);
        }
        g_p[i] = v;
    }
    if (i < GN) {
        double ang = -2.0 * PI * (double)i / (double)GN;
        double s, c;
        sincos(ang, &s, &c);
        g_W500f[i] = make_float2((float)c, (float)s);
        g_W500i[i] = make_float2((float)c, (float)(-s));
    }
    if (i < 2 * 200 * 200) g_canvas[i] = 0.f;
    if (i < 128) g_intens[i] = 0.f;
    if (i < GN * GN) {
        float s, c;
        sincosf(mp[i], &s, &c);
        float m = mr[i];
        float2 b = B1[i];
        float er = m * c, ei = m * s;
        g_field[i] = make_float2(b.x * er - b.y * ei, b.x * ei + b.y * er);
        int u = i / GN, v2 = i % GN;
        int su = (u + 250) % GN, sv = (v2 + 250) % GN;
        g_tg[i] = sK * gam[su * GN + sv];
    }
}

// ---------------- M build via sliding-window recurrence --------------------
// M[k,m] = W^{km} * G_m(k),  G_m = sum_{j=-m}^{499-m} W^{kj} p[500+j].
// 8 segments per k, each with a fresh direct-sum start (error containment).
__global__ __launch_bounds__(128) void k_buildM() {
    __shared__ float2 sWf[GN];
    __shared__ float2 sp[1000];
    for (int i = threadIdx.x; i < 1000; i += 128) {
        if (i < GN) sWf[i] = g_W500f[i];
        sp[i] = g_p[i];
    }
    __syncthreads();

    int t = blockIdx.x * blockDim.x + threadIdx.x;
    if (t >= GN * 8) return;
    int k = t >> 3, seg = t & 7;
    int m0 = seg * SEG;
    int mend = m0 + SEG; if (mend > GN) mend = GN;

    // phase 1: direct window sum at m0, walking j = -m0 .. 499-m0
    int idx0 = (k * m0) % GN;
    int idx = (GN - idx0) % GN;       // (k * (-m0)) mod 500
    float gx = 0.f, gy = 0.f;
    for (int s = 0; s < GN; s++) {
        float2 w = sWf[idx];
        float2 pv = sp[500 - m0 + s];
        gx = fmaf(w.x, pv.x, gx); gx = fmaf(-w.y, pv.y, gx);
        gy = fmaf(w.x, pv.y, gy); gy = fmaf(w.y, pv.x, gy);
        idx += k; if (idx >= GN) idx -= GN;
    }

    // phase 2: slide m0 -> mend-1
    int idx3 = idx0;                           // (k*m) % 500
    int idx1 = idx0 + k; if (idx1 >= GN) idx1 -= GN;   // (k*(m+1)) % 500
    int idx2 = (k * (499 - m0)) % GN;          // (k*(499-m)) % 500
    for (int m = m0; m < mend; m++) {
        float2 w3 = sWf[idx3];
        float Mx = (w3.x * gx - w3.y * gy) * 1e-3f;
        float My = (w3.x * gy + w3.y * gx) * 1e-3f;
        g_MT[m * MTS + k] = make_float2(Mx, My);
        // G_{m+1} = G_m + conj(W^{k(m+1)}) p[499-m] - W^{k(499-m)} p[999-m]
        float2 w1 = sWf[idx1];
        float2 pa = sp[499 - m];
        gx = fmaf(w1.x, pa.x, gx); gx = fmaf(w1.y, pa.y, gx);
        gy = fmaf(w1.x, pa.y, gy); gy = fmaf(-w1.y, pa.x, gy);
        float2 w2 = sWf[idx2];
        float2 pb = sp[999 - m];
        gx = fmaf(-w2.x, pb.x, gx); gx = fmaf(w2.y, pb.y, gx);
        gy = fmaf(-w2.x, pb.y, gy); gy = fmaf(-w2.y, pb.x, gy);
        idx3 += k; if (idx3 >= GN) idx3 -= GN;
        idx1 += k; if (idx1 >= GN) idx1 -= GN;
        idx2 -= k; if (idx2 < 0) idx2 += GN;
    }
}

// ---------------- apply pass: out[k*500+r] = sum_n in[r,n] * M[k,n] --------
// Pack-free inner loop: w staged as (re,re,im,im), x staged as (re,im,-im,re).
__global__ __launch_bounds__(128) void k_apply(const float2* __restrict__ in,
                                               float2* __restrict__ out) {
    extern __shared__ float4 sh[];
    float4* sw = sh;             // [KK][TK]
    float4* sx = sh + KK * TK;   // [KK][TR]

    int k0 = blockIdx.x * TK;
    int r0 = blockIdx.y * TR;
    int tid = threadIdx.x;
    int tkg = tid & 15;
    int trg = tid >> 4;

    u64 acc[4][4] = {};

    for (int n0 = 0; n0 < GN; n0 += KK) {
        __syncthreads();
        for (int i = tid; i < TK * KK; i += 128) {
            int kk = i & 63, nn = i >> 6;
            float2 w = g_MT[(size_t)(n0 + nn) * MTS + k0 + kk];
            sw[nn * TK + kk] = make_float4(w.x, w.x, w.y, w.y);
        }
        for (int i = tid; i < TR * KK; i += 128) {
            int nn = i % KK, rr = i / KK;
            int r = r0 + rr;
            float2 v = make_float2(0.f, 0.f);
            if (r < GN) v = in[(size_t)r * GN + n0 + nn];
            sx[nn * TR + rr] = make_float4(v.x, v.y, -v.y, v.x);
        }
        __syncthreads();

#pragma unroll 2
        for (int nn = 0; nn < KK; nn++) {
            const ulonglong2* wrow = (const ulonglong2*)(sw + nn * TK);
            const ulonglong2* xrow = (const ulonglong2*)(sx + nn * TR);
            ulonglong2 w0 = wrow[4 * tkg + 0];
            ulonglong2 w1 = wrow[4 * tkg + 1];
            ulonglong2 w2 = wrow[4 * tkg + 2];
            ulonglong2 w3 = wrow[4 * tkg + 3];
            ulonglong2 x0 = xrow[4 * trg + 0];
            ulonglong2 x1 = xrow[4 * trg + 1];
            ulonglong2 x2 = xrow[4 * trg + 2];
            ulonglong2 x3 = xrow[4 * trg + 3];

            acc[0][0] = ffma2(w0.x, x0.x, acc[0][0]); acc[0][0] = ffma2(w0.y, x0.y, acc[0][0]);
            acc[0][1] = ffma2(w0.x, x1.x, acc[0][1]); acc[0][1] = ffma2(w0.y, x1.y, acc[0][1]);
            acc[0][2] = ffma2(w0.x, x2.x, acc[0][2]); acc[0][2] = ffma2(w0.y, x2.y, acc[0][2]);
            acc[0][3] = ffma2(w0.x, x3.x, acc[0][3]); acc[0][3] = ffma2(w0.y, x3.y, acc[0][3]);
            acc[1][0] = ffma2(w1.x, x0.x, acc[1][0]); acc[1][0] = ffma2(w1.y, x0.y, acc[1][0]);
            acc[1][1] = ffma2(w1.x, x1.x, acc[1][1]); acc[1][1] = ffma2(w1.y, x1.y, acc[1][1]);
            acc[1][2] = ffma2(w1.x, x2.x, acc[1][2]); acc[1][2] = ffma2(w1.y, x2.y, acc[1][2]);
            acc[1][3] = ffma2(w1.x, x3.x, acc[1][3]); acc[1][3] = ffma2(w1.y, x3.y, acc[1][3]);
            acc[2][0] = ffma2(w2.x, x0.x, acc[2][0]); acc[2][0] = ffma2(w2.y, x0.y, acc[2][0]);
            acc[2][1] = ffma2(w2.x, x1.x, acc[2][1]); acc[2][1] = ffma2(w2.y, x1.y, acc[2][1]);
            acc[2][2] = ffma2(w2.x, x2.x, acc[2][2]); acc[2][2] = ffma2(w2.y, x2.y, acc[2][2]);
            acc[2][3] = ffma2(w2.x, x3.x, acc[2][3]); acc[2][3] = ffma2(w2.y, x3.y, acc[2][3]);
            acc[3][0] = ffma2(w3.x, x0.x, acc[3][0]); acc[3][0] = ffma2(w3.y, x0.y, acc[3][0]);
            acc[3][1] = ffma2(w3.x, x1.x, acc[3][1]); acc[3][1] = ffma2(w3.y, x1.y, acc[3][1]);
            acc[3][2] = ffma2(w3.x, x2.x, acc[3][2]); acc[3][2] = ffma2(w3.y, x2.y, acc[3][2]);
            acc[3][3] = ffma2(w3.x, x3.x, acc[3][3]); acc[3][3] = ffma2(w3.y, x3.y, acc[3][3]);
        }
    }

    int rb = r0 + 4 * trg;
    if (rb < GN) {
#pragma unroll
        for (int q = 0; q < 4; q++) {
            int k = k0 + 4 * tkg + q;
            if (k >= GN) continue;
            float2 c0 = unpk(acc[q][0]), c1 = unpk(acc[q][1]);
            float2 c2 = unpk(acc[q][2]), c3 = unpk(acc[q][3]);
            float4* dst = (float4*)&out[(size_t)k * GN + rb];
            dst[0] = make_float4(c0.x, c0.y, c1.x, c1.y);
            dst[1] = make_float4(c2.x, c2.y, c3.x, c3.y);
        }
    }
}

// ---------------- per-emitter intensity: warp-per-emitter ------------------
__global__ __launch_bounds__(128) void k_emit(const int* __restrict__ xyz) {
    __shared__ float2 sfo[GN];
    __shared__ float  stg[GN];
    __shared__ float2 sW[GN];
    int u = blockIdx.x;
    int eBase = blockIdx.y * 32;

    const float2* fo = g_B + (size_t)u * GN;   // FO lives in g_B
    const float*  tg = g_tg + (size_t)u * GN;
    for (int i = threadIdx.x; i < GN; i += 128) {
        sfo[i] = fo[i];
        stg[i] = tg[i];
        sW[i]  = g_W500i[i];
    }
    __syncthreads();

    int lane = threadIdx.x & 31;
    int wid = threadIdx.x >> 5;

    for (int ee = wid; ee < 32; ee += 4) {
        int e = eBase + ee;
        int x0 = xyz[e * 3 + 0];
        int z = xyz[e * 3 + 2];
        float xf = (float)(x0 - 100);
        int c = 249 + z;
        int idx = (c * lane) % GN;
        int step = (c * 32) % GN;

        float sx = 0.f, sy = 0.f;
        for (int v = lane; v < GN; v += 32) {
            float arg = stg[v] * xf;  // f32 rounding matches reference
            float nq = rintf(arg * 0.15915494309189535f);
            float rr = fmaf(nq, -6.28125f, arg);
            rr = fmaf(nq, -1.9353072e-3f, rr);
            float sn, cs;
            __sincosf(rr, &sn, &cs);
            float2 f = sfo[v];
            float pr = f.x * cs - f.y * sn;
            float pi = f.x * sn + f.y * cs;
            float2 w = sW[idx];
            sx = fmaf(pr, w.x, sx); sx = fmaf(-pi, w.y, sx);
            sy = fmaf(pr, w.y, sy); sy = fmaf(pi, w.x, sy);
            idx += step; if (idx >= GN) idx -= GN;
        }
#pragma unroll
        for (int o = 16; o > 0; o >>= 1) {
            sx += __shfl_down_sync(0xffffffffu, sx, o);
            sy += __shfl_down_sync(0xffffffffu, sy, o);
        }
        if (lane == 0)
            atomicAdd(&g_intens[e], (sx * sx + sy * sy) * 8e-9f);  // 1/500^3
    }
}

// ---------------- scatter psf patches into canvas --------------------------
__global__ void k_scatter(const int* __restrict__ xyz,
                          const float* __restrict__ psf) {
    int tid = blockIdx.x * blockDim.x + threadIdx.x;
    if (tid >= 128 * 961) return;
    int e = tid / 961, p = tid % 961;
    int b = e >> 6;
    int x0 = xyz[e * 3 + 0];
    int y0 = xyz[e * 3 + 1];
    int z = xyz[e * 3 + 2];
    int r = p / 31, cc = p % 31;
    float val = psf[z * 961 + p] * g_intens[e];
    int row = x0 + r - 15;
    int col = y0 + cc - 15;
    atomicAdd(&g_canvas[b * 40000 + row * 200 + col], val);
}

// ---------------- noise model + output -------------------------------------
__global__ void k_final(const float* __restrict__ ng,
                        const float* __restrict__ np_,
                        float* __restrict__ out) {
    int i = blockIdx.x * blockDim.x + threadIdx.x;
    if (i >= 2 * 200 * 200) return;
    float a = g_canvas[i] / 50000.0f + 100.0f;  // imgs3D + UNIF_BG
    float b = a + 100000.0f;
    float t = fmaf(2.0e8f, ng[i], 3.0e8f);
    float inp = b + t;
    if (inp <= 0.0f) inp = 0.0f;
    float noisy = inp + 100.0f * sqrtf(inp) * np_[i];
    if (noisy <= 10.0f) noisy = 1.0f;
    noisy = fminf(noisy, 4.0e9f);
    out[i] = noisy / 4.0e9f;
}

// ---------------------------------------------------------------------------
extern "C" void kernel_launch(void* const* d_in, const int* in_sizes, int n_in,
                              void* d_out, int out_size) {
    const float*  mask_param = (const float*)d_in[0];
    const int*    xyz        = (const int*)d_in[1];
    // d_in[2] = nphotons (unused by reference)
    const float2* B1         = (const float2*)d_in[3];
    // d_in[4] = Q1 (replaced by separable p-vector)
    const float*  mask_real  = (const float*)d_in[5];
    const float*  gamma_c    = (const float*)d_in[6];
    const float*  psf        = (const float*)d_in[7];
    const float*  ngauss     = (const float*)d_in[8];
    const float*  npoiss     = (const float*)d_in[9];
    float*        out        = (float*)d_out;

    double Kd = 2.0 * 1.33 * 3.14159265358979323846 / 5.61e-7;
    float sK = (float)(Kd * 1e-6);

    float2 *fld, *bA, *bB;
    cudaGetSymbolAddress((void**)&fld, g_field);
    cudaGetSymbolAddress((void**)&bA, g_A);
    cudaGetSymbolAddress((void**)&bB, g_B);

    const int BT = 256;
    const int SMEM_APPLY = (TK + TR) * KK * (int)sizeof(float4);  // 76.8KB
    static int attr_done = 0;
    cudaFuncSetAttribute(k_apply, cudaFuncAttributeMaxDynamicSharedMemorySize,
                         SMEM_APPLY);
    (void)attr_done;

    // fused setup
    k_prep<<<(GN * GN + BT - 1) / BT, BT>>>(mask_param, mask_real, B1,
                                            gamma_c, sK);

    // M = 1e-3 * F * T via sliding-window recurrence (transposed into g_MT)
    k_buildM<<<(GN * 8 + 127) / 128, 128>>>();

    // FO = M f M^T  (two transposing apply-passes) -> g_B
    dim3 pg((GN + TK - 1) / TK, (GN + TR - 1) / TR);  // 8 x 16 = 128 blocks
    k_apply<<<pg, 128, SMEM_APPLY>>>(fld, bA);
    k_apply<<<pg, 128, SMEM_APPLY>>>(bA, bB);

    // per-emitter intensities (warp-per-emitter, 32 emitters per block)
    k_emit<<<dim3(GN, 4), 128>>>(xyz);

    // patches -> canvas
    k_scatter<<<(128 * 961 + BT - 1) / BT, BT>>>(xyz, psf);

    // noise model -> output
    k_final<<<(2 * 200 * 200 + BT - 1) / BT, BT>>>(ngauss, npoiss, out);
}

// round 6
// speedup vs baseline: 2.0942x; 2.0942x over previous
#include <cuda_runtime.h>
#include <math.h>

// ---------------------------------------------------------------------------
// PhysicalLayer forward, sm_103a.
//   FO = M f M^T, M = F*T built by O(N^2) sliding-window recurrence.
//   2 apply GEMMs: 256 threads, 2kx4r microtile, warp-uniform x (broadcast
//   LDS), double-buffered smem. Warp-per-emitter Parseval intensities,
//   scatter + noise model.
// ---------------------------------------------------------------------------

#define GN  500
#define TK  64
#define TR  32
#define KK  50
#define MTS 512
#define SEG 63

typedef unsigned long long u64;

__device__ float2 g_field[GN * GN];
__device__ float2 g_A[GN * GN];
__device__ float2 g_B[GN * GN];
__device__ float2 g_MT[GN * MTS];   // MT[m*512 + k] = M[k,m]; cols 500.. stay 0
__device__ float  g_tg[GN * GN];
__device__ float2 g_p[1024];
__device__ float2 g_W500f[GN];
__device__ float2 g_W500i[GN];
__device__ float  g_intens[128];
__device__ float  g_canvas[2 * 200 * 200];

// ---------------- f32x2 packed helpers -------------------------------------
__device__ __forceinline__ u64 ffma2(u64 a, u64 b, u64 c) {
    u64 d;
    asm("fma.rn.f32x2 %0, %1, %2, %3;" : "=l"(d) : "l"(a), "l"(b), "l"(c));
    return d;
}
__device__ __forceinline__ u64 pk2(float lo, float hi) {
    u64 r;
    asm("mov.b64 %0, {%1, %2};" : "=l"(r) : "f"(lo), "f"(hi));
    return r;
}
__device__ __forceinline__ float2 unpk(u64 v) {
    float lo, hi;
    asm("mov.b64 {%0, %1}, %2;" : "=f"(lo), "=f"(hi) : "l"(v));
    return make_float2(lo, hi);
}

// ---------------- fused prep: tables + zero + field + tg -------------------
__global__ void k_prep(const float* __restrict__ mp,
                       const float* __restrict__ mr,
                       const float2* __restrict__ B1,
                       const float* __restrict__ gam, float sK) {
    int i = blockIdx.x * blockDim.x + threadIdx.x;
    const double PI = 3.14159265358979323846;
    if (i < 1024) {
        float2 v = make_float2(0.f, 0.f);
        if (i < 1000) {
            double alpha = PI * 1.33 / (5.61e-7 * 0.006);
            double x = (double)(i - 499) * 1e-6;
            double th = alpha * x * x;
            double s, c;
            sincos(th, &s, &c);
            v = make_float2((float)c, (float)s);
        }
        g_p[i] = v;
    }
    if (i < GN) {
        double ang = -2.0 * PI * (double)i / (double)GN;
        double s, c;
        sincos(ang, &s, &c);
        g_W500f[i] = make_float2((float)c, (float)s);
        g_W500i[i] = make_float2((float)c, (float)(-s));
    }
    if (i < 2 * 200 * 200) g_canvas[i] = 0.f;
    if (i < 128) g_intens[i] = 0.f;
    if (i < GN * GN) {
        float s, c;
        sincosf(mp[i], &s, &c);
        float m = mr[i];
        float2 b = B1[i];
        float er = m * c, ei = m * s;
        g_field[i] = make_float2(b.x * er - b.y * ei, b.x * ei + b.y * er);
        int u = i / GN, v2 = i % GN;
        int su = (u + 250) % GN, sv = (v2 + 250) % GN;
        g_tg[i] = sK * gam[su * GN + sv];
    }
}

// ---------------- M build via sliding-window recurrence --------------------
__global__ __launch_bounds__(128) void k_buildM() {
    __shared__ float2 sWf[GN];
    __shared__ float2 sp[1000];
    for (int i = threadIdx.x; i < 1000; i += 128) {
        if (i < GN) sWf[i] = g_W500f[i];
        sp[i] = g_p[i];
    }
    __syncthreads();

    int t = blockIdx.x * blockDim.x + threadIdx.x;
    if (t >= GN * 8) return;
    int k = t >> 3, seg = t & 7;
    int m0 = seg * SEG;
    int mend = m0 + SEG; if (mend > GN) mend = GN;

    int idx0 = (k * m0) % GN;
    int idx = (GN - idx0) % GN;
    float gx = 0.f, gy = 0.f;
    for (int s = 0; s < GN; s++) {
        float2 w = sWf[idx];
        float2 pv = sp[500 - m0 + s];
        gx = fmaf(w.x, pv.x, gx); gx = fmaf(-w.y, pv.y, gx);
        gy = fmaf(w.x, pv.y, gy); gy = fmaf(w.y, pv.x, gy);
        idx += k; if (idx >= GN) idx -= GN;
    }

    int idx3 = idx0;
    int idx1 = idx0 + k; if (idx1 >= GN) idx1 -= GN;
    int idx2 = (k * (499 - m0)) % GN;
    for (int m = m0; m < mend; m++) {
        float2 w3 = sWf[idx3];
        float Mx = (w3.x * gx - w3.y * gy) * 1e-3f;
        float My = (w3.x * gy + w3.y * gx) * 1e-3f;
        g_MT[m * MTS + k] = make_float2(Mx, My);
        float2 w1 = sWf[idx1];
        float2 pa = sp[499 - m];
        gx = fmaf(w1.x, pa.x, gx); gx = fmaf(w1.y, pa.y, gx);
        gy = fmaf(w1.x, pa.y, gy); gy = fmaf(-w1.y, pa.x, gy);
        float2 w2 = sWf[idx2];
        float2 pb = sp[999 - m];
        gx = fmaf(-w2.x, pb.x, gx); gx = fmaf(w2.y, pb.y, gx);
        gy = fmaf(-w2.x, pb.y, gy); gy = fmaf(-w2.y, pb.x, gy);
        idx3 += k; if (idx3 >= GN) idx3 -= GN;
        idx1 += k; if (idx1 >= GN) idx1 -= GN;
        idx2 -= k; if (idx2 < 0) idx2 += GN;
    }
}

// ---------------- apply pass: out[k*500+r] = sum_n in[r,n] * M[k,n] --------
// 256 threads: tkg=tid&31 (2 k's each), trg=tid>>5 = warp id (4 r's each).
// x is warp-uniform -> broadcast LDS. Double-buffered smem.
#define WBYTES (KK * TK * 8)                 // 25600: float2 [KK][TK]
#define XBYTES (KK * TR * 16)                // 25600: float4 [KK][TR]
#define BUFBYTES (WBYTES + XBYTES)           // 51200
#define NCHUNK 10

__global__ __launch_bounds__(256, 1) void k_apply(const float2* __restrict__ in,
                                                  float2* __restrict__ out) {
    extern __shared__ char sh[];
    int k0 = blockIdx.x * TK;
    int r0 = blockIdx.y * TR;
    int tid = threadIdx.x;
    int tkg = tid & 31;
    int trg = tid >> 5;

    u64 acc[2][4] = {};

    // stage chunk 0
    {
        float2* swb = (float2*)(sh);
        float4* sxb = (float4*)(sh + WBYTES);
#pragma unroll
        for (int j = 0; j < 7; j++) {
            int i = tid + j * 256;
            if (i < 1600) {
                int nn = i >> 5, kk2 = i & 31;
                ((float4*)swb)[nn * 32 + kk2] =
                    *(const float4*)&g_MT[(size_t)nn * MTS + k0 + 2 * kk2];
            }
        }
#pragma unroll
        for (int j = 0; j < 7; j++) {
            int i = tid + j * 256;
            if (i < 1600) {
                int rr = i & 31, nn = i >> 5;
                int r = r0 + rr;
                float2 v = make_float2(0.f, 0.f);
                if (r < GN) v = in[(size_t)r * GN + nn];
                sxb[nn * 32 + rr] = make_float4(v.x, v.y, -v.y, v.x);
            }
        }
    }
    __syncthreads();

    for (int c = 0; c < NCHUNK; c++) {
        // prefetch chunk c+1 into registers
        float4 pw[7];
        float2 px[7];
        if (c + 1 < NCHUNK) {
            int n0p = (c + 1) * KK;
#pragma unroll
            for (int j = 0; j < 7; j++) {
                int i = tid + j * 256;
                if (i < 1600) {
                    int nn = i >> 5, kk2 = i & 31;
                    pw[j] = *(const float4*)&g_MT[(size_t)(n0p + nn) * MTS +
                                                  k0 + 2 * kk2];
                }
            }
#pragma unroll
            for (int j = 0; j < 7; j++) {
                int i = tid + j * 256;
                if (i < 1600) {
                    int rr = i & 31, nn = i >> 5;
                    int r = r0 + rr;
                    float2 v = make_float2(0.f, 0.f);
                    if (r < GN) v = in[(size_t)r * GN + n0p + nn];
                    px[j] = v;
                }
            }
        }

        // compute on buffer c&1
        {
            const char* base = sh + (c & 1) * BUFBYTES;
            const float4* swc = (const float4*)base;              // [KK][32]
            const ulonglong2* sxc = (const ulonglong2*)(base + WBYTES); // [KK][32]
#pragma unroll 5
            for (int nn = 0; nn < KK; nn++) {
                float4 wv = swc[nn * 32 + tkg];
                u64 wR0 = pk2(wv.x, wv.x), wI0 = pk2(wv.y, wv.y);
                u64 wR1 = pk2(wv.z, wv.z), wI1 = pk2(wv.w, wv.w);
                ulonglong2 x0 = sxc[nn * 32 + 4 * trg + 0];
                ulonglong2 x1 = sxc[nn * 32 + 4 * trg + 1];
                ulonglong2 x2 = sxc[nn * 32 + 4 * trg + 2];
                ulonglong2 x3 = sxc[nn * 32 + 4 * trg + 3];

                acc[0][0] = ffma2(wR0, x0.x, acc[0][0]);
                acc[0][0] = ffma2(wI0, x0.y, acc[0][0]);
                acc[0][1] = ffma2(wR0, x1.x, acc[0][1]);
                acc[0][1] = ffma2(wI0, x1.y, acc[0][1]);
                acc[0][2] = ffma2(wR0, x2.x, acc[0][2]);
                acc[0][2] = ffma2(wI0, x2.y, acc[0][2]);
                acc[0][3] = ffma2(wR0, x3.x, acc[0][3]);
                acc[0][3] = ffma2(wI0, x3.y, acc[0][3]);
                acc[1][0] = ffma2(wR1, x0.x, acc[1][0]);
                acc[1][0] = ffma2(wI1, x0.y, acc[1][0]);
                acc[1][1] = ffma2(wR1, x1.x, acc[1][1]);
                acc[1][1] = ffma2(wI1, x1.y, acc[1][1]);
                acc[1][2] = ffma2(wR1, x2.x, acc[1][2]);
                acc[1][2] = ffma2(wI1, x2.y, acc[1][2]);
                acc[1][3] = ffma2(wR1, x3.x, acc[1][3]);
                acc[1][3] = ffma2(wI1, x3.y, acc[1][3]);
            }
        }

        // store prefetched chunk into the other buffer
        if (c + 1 < NCHUNK) {
            char* base = sh + ((c + 1) & 1) * BUFBYTES;
            float4* swb4 = (float4*)base;
            float4* sxb = (float4*)(base + WBYTES);
#pragma unroll
            for (int j = 0; j < 7; j++) {
                int i = tid + j * 256;
                if (i < 1600) {
                    int nn = i >> 5, kk2 = i & 31;
                    swb4[nn * 32 + kk2] = pw[j];
                }
            }
#pragma unroll
            for (int j = 0; j < 7; j++) {
                int i = tid + j * 256;
                if (i < 1600) {
                    int rr = i & 31, nn = i >> 5;
                    float2 v = px[j];
                    sxb[nn * 32 + rr] = make_float4(v.x, v.y, -v.y, v.x);
                }
            }
        }
        __syncthreads();
    }

    // write out: k = k0 + 2*tkg + q, r = r0 + 4*trg + s
    int rb = r0 + 4 * trg;
#pragma unroll
    for (int q = 0; q < 2; q++) {
        int k = k0 + 2 * tkg + q;
        if (k >= GN) continue;
        float2 c0 = unpk(acc[q][0]), c1 = unpk(acc[q][1]);
        float2 c2 = unpk(acc[q][2]), c3 = unpk(acc[q][3]);
        if (rb + 3 < GN) {
            float4* dst = (float4*)&out[(size_t)k * GN + rb];
            dst[0] = make_float4(c0.x, c0.y, c1.x, c1.y);
            dst[1] = make_float4(c2.x, c2.y, c3.x, c3.y);
        } else {
            float2 cs[4] = {c0, c1, c2, c3};
#pragma unroll
            for (int s = 0; s < 4; s++)
                if (rb + s < GN) out[(size_t)k * GN + rb + s] = cs[s];
        }
    }
}

// ---------------- per-emitter intensity: warp-per-emitter ------------------
__global__ __launch_bounds__(128) void k_emit(const int* __restrict__ xyz) {
    __shared__ float2 sfo[GN];
    __shared__ float  stg[GN];
    __shared__ float2 sW[GN];
    int u = blockIdx.x;
    int eBase = blockIdx.y * 32;

    const float2* fo = g_B + (size_t)u * GN;   // FO lives in g_B
    const float*  tg = g_tg + (size_t)u * GN;
    for (int i = threadIdx.x; i < GN; i += 128) {
        sfo[i] = fo[i];
        stg[i] = tg[i];
        sW[i]  = g_W500i[i];
    }
    __syncthreads();

    int lane = threadIdx.x & 31;
    int wid = threadIdx.x >> 5;

    for (int ee = wid; ee < 32; ee += 4) {
        int e = eBase + ee;
        int x0 = xyz[e * 3 + 0];
        int z = xyz[e * 3 + 2];
        float xf = (float)(x0 - 100);
        int c = 249 + z;
        int idx = (c * lane) % GN;
        int step = (c * 32) % GN;

        float sx = 0.f, sy = 0.f;
        for (int v = lane; v < GN; v += 32) {
            float arg = stg[v] * xf;  // f32 rounding matches reference
            float nq = rintf(arg * 0.15915494309189535f);
            float rr = fmaf(nq, -6.28125f, arg);
            rr = fmaf(nq, -1.9353072e-3f, rr);
            float sn, cs;
            __sincosf(rr, &sn, &cs);
            float2 f = sfo[v];
            float pr = f.x * cs - f.y * sn;
            float pi = f.x * sn + f.y * cs;
            float2 w = sW[idx];
            sx = fmaf(pr, w.x, sx); sx = fmaf(-pi, w.y, sx);
            sy = fmaf(pr, w.y, sy); sy = fmaf(pi, w.x, sy);
            idx += step; if (idx >= GN) idx -= GN;
        }
#pragma unroll
        for (int o = 16; o > 0; o >>= 1) {
            sx += __shfl_down_sync(0xffffffffu, sx, o);
            sy += __shfl_down_sync(0xffffffffu, sy, o);
        }
        if (lane == 0)
            atomicAdd(&g_intens[e], (sx * sx + sy * sy) * 8e-9f);  // 1/500^3
    }
}

// ---------------- scatter psf patches into canvas --------------------------
__global__ void k_scatter(const int* __restrict__ xyz,
                          const float* __restrict__ psf) {
    int tid = blockIdx.x * blockDim.x + threadIdx.x;
    if (tid >= 128 * 961) return;
    int e = tid / 961, p = tid % 961;
    int b = e >> 6;
    int x0 = xyz[e * 3 + 0];
    int y0 = xyz[e * 3 + 1];
    int z = xyz[e * 3 + 2];
    int r = p / 31, cc = p % 31;
    float val = psf[z * 961 + p] * g_intens[e];
    int row = x0 + r - 15;
    int col = y0 + cc - 15;
    atomicAdd(&g_canvas[b * 40000 + row * 200 + col], val);
}

// ---------------- noise model + output -------------------------------------
__global__ void k_final(const float* __restrict__ ng,
                        const float* __restrict__ np_,
                        float* __restrict__ out) {
    int i = blockIdx.x * blockDim.x + threadIdx.x;
    if (i >= 2 * 200 * 200) return;
    float a = g_canvas[i] / 50000.0f + 100.0f;  // imgs3D + UNIF_BG
    float b = a + 100000.0f;
    float t = fmaf(2.0e8f, ng[i], 3.0e8f);
    float inp = b + t;
    if (inp <= 0.0f) inp = 0.0f;
    float noisy = inp + 100.0f * sqrtf(inp) * np_[i];
    if (noisy <= 10.0f) noisy = 1.0f;
    noisy = fminf(noisy, 4.0e9f);
    out[i] = noisy / 4.0e9f;
}

// ---------------------------------------------------------------------------
extern "C" void kernel_launch(void* const* d_in, const int* in_sizes, int n_in,
                              void* d_out, int out_size) {
    const float*  mask_param = (const float*)d_in[0];
    const int*    xyz        = (const int*)d_in[1];
    // d_in[2] = nphotons (unused by reference)
    const float2* B1         = (const float2*)d_in[3];
    // d_in[4] = Q1 (replaced by separable p-vector)
    const float*  mask_real  = (const float*)d_in[5];
    const float*  gamma_c    = (const float*)d_in[6];
    const float*  psf        = (const float*)d_in[7];
    const float*  ngauss     = (const float*)d_in[8];
    const float*  npoiss     = (const float*)d_in[9];
    float*        out        = (float*)d_out;

    double Kd = 2.0 * 1.33 * 3.14159265358979323846 / 5.61e-7;
    float sK = (float)(Kd * 1e-6);

    float2 *fld, *bA, *bB;
    cudaGetSymbolAddress((void**)&fld, g_field);
    cudaGetSymbolAddress((void**)&bA, g_A);
    cudaGetSymbolAddress((void**)&bB, g_B);

    const int BT = 256;
    const int SMEM_APPLY = 2 * BUFBYTES;  // 102.4KB
    cudaFuncSetAttribute(k_apply, cudaFuncAttributeMaxDynamicSharedMemorySize,
                         SMEM_APPLY);

    // fused setup
    k_prep<<<(GN * GN + BT - 1) / BT, BT>>>(mask_param, mask_real, B1,
                                            gamma_c, sK);

    // M = 1e-3 * F * T via sliding-window recurrence (transposed into g_MT)
    k_buildM<<<(GN * 8 + 127) / 128, 128>>>();

    // FO = M f M^T  (two transposing apply-passes) -> g_B
    dim3 pg((GN + TK - 1) / TK, (GN + TR - 1) / TR);  // 8 x 16 = 128 blocks
    k_apply<<<pg, 256, SMEM_APPLY>>>(fld, bA);
    k_apply<<<pg, 256, SMEM_APPLY>>>(bA, bB);

    // per-emitter intensities (warp-per-emitter, 32 emitters per block)
    k_emit<<<dim3(GN, 4), 128>>>(xyz);

    // patches -> canvas
    k_scatter<<<(128 * 961 + BT - 1) / BT, BT>>>(xyz, psf);

    // noise model -> output
    k_final<<<(2 * 200 * 200 + BT - 1) / BT, BT>>>(ngauss, npoiss, out);
}